// round 16
// baseline (speedup 1.0000x reference)
#include <cuda_runtime.h>
#include <cuda_bf16.h>
#include <math.h>

// ---------------------------------------------------------------------------
// VQ-VAE forward. Encoder path (convs, BN, VQ chains) is bit-load-bearing and
// byte-identical to the R14/R15 passing config. Decoder (1e-3 tolerance):
//  - tconv multi-co: 2x2 outputs x COG channel group per thread, weights in
//    smem -> amortizes the 3x3xCI window loads across COG co's
//  - decoder BN: fused single-pass sum+sumsq partials (deterministic order)
// ---------------------------------------------------------------------------

#define N_BATCH 32
#define SL 32

__device__ float g_h1[8388608];
__device__ float g_h2[4194304];
__device__ float g_h3[2097152];
__device__ float g_ze[1048576];
__device__ float g_zq[1048576];
__device__ int   g_lat[32768];
__device__ float g_d1[2097152];
__device__ float g_t1[4194304];
__device__ float g_t2[8388608];

__device__ float g_part[64 * SL];
__device__ float g_part2[64 * SL];
__device__ float g_mean[64];
__device__ float g_sdev[64];
__device__ float g_e2[512];

// ------------------------------ BatchNorm (encoder: bit-exact two-pass) -----

__global__ void k_bn_partial(const float* __restrict__ x, int C, int plane, int pass) {
    int c = blockIdx.x / SL;
    int s = blockIdx.x % SL;
    unsigned per = (unsigned)N_BATCH * (unsigned)plane;
    float m = (pass == 1) ? g_mean[c] : 0.f;
    float acc = 0.f;
    unsigned step = (unsigned)SL * blockDim.x;
    for (unsigned i = (unsigned)s * blockDim.x + threadIdx.x; i < per; i += step) {
        unsigned n = i / (unsigned)plane;
        unsigned p = i - n * (unsigned)plane;
        float v = x[((unsigned)(n * C + c)) * (unsigned)plane + p];
        if (pass == 1) { float d = __fsub_rn(v, m); acc = __fadd_rn(acc, __fmul_rn(d, d)); }
        else           { acc = __fadd_rn(acc, v); }
    }
    __shared__ float ss[256];
    ss[threadIdx.x] = acc;
    __syncthreads();
    for (int st = 128; st > 0; st >>= 1) {
        if (threadIdx.x < st) ss[threadIdx.x] = __fadd_rn(ss[threadIdx.x], ss[threadIdx.x + st]);
        __syncthreads();
    }
    if (threadIdx.x == 0) g_part[c * SL + s] = ss[0];
}

__global__ void k_bn_combine(int C, float inv_n, int pass) {
    int c = threadIdx.x;
    if (c >= C) return;
    float s = 0.f;
#pragma unroll 1
    for (int i = 0; i < SL; i++) s = __fadd_rn(s, g_part[c * SL + i]);
    float v = __fmul_rn(s, inv_n);
    if (pass == 0) g_mean[c] = v;
    else           g_sdev[c] = __fsqrt_rn(__fadd_rn(v, 1e-5f));
}

// ------------------------------ BatchNorm (decoder: fused single-pass) ------

__global__ void k_bn_partial2(const float* __restrict__ x, int C, int plane) {
    int c = blockIdx.x / SL;
    int s = blockIdx.x % SL;
    unsigned per = (unsigned)N_BATCH * (unsigned)plane;
    float acc = 0.f, acc2 = 0.f;
    unsigned step = (unsigned)SL * blockDim.x;
    for (unsigned i = (unsigned)s * blockDim.x + threadIdx.x; i < per; i += step) {
        unsigned n = i / (unsigned)plane;
        unsigned p = i - n * (unsigned)plane;
        float v = x[((unsigned)(n * C + c)) * (unsigned)plane + p];
        acc  += v;
        acc2 = fmaf(v, v, acc2);
    }
    __shared__ float ss[256], s2[256];
    ss[threadIdx.x] = acc; s2[threadIdx.x] = acc2;
    __syncthreads();
    for (int st = 128; st > 0; st >>= 1) {
        if (threadIdx.x < st) {
            ss[threadIdx.x] += ss[threadIdx.x + st];
            s2[threadIdx.x] += s2[threadIdx.x + st];
        }
        __syncthreads();
    }
    if (threadIdx.x == 0) {
        g_part[c * SL + s]  = ss[0];
        g_part2[c * SL + s] = s2[0];
    }
}

__global__ void k_bn_combine2(int C, float inv_n) {
    int c = threadIdx.x;
    if (c >= C) return;
    float s = 0.f, q = 0.f;
#pragma unroll 1
    for (int i = 0; i < SL; i++) { s += g_part[c * SL + i]; q += g_part2[c * SL + i]; }
    float m = s * inv_n;
    float var = fmaf(-m, m, q * inv_n);
    g_mean[c] = m;
    g_sdev[c] = __fsqrt_rn(var + 1e-5f);
}

__global__ void k_bn_apply(float* __restrict__ x, const float* __restrict__ g,
                           const float* __restrict__ be,
                           int C, int plane, unsigned total, int relu) {
    unsigned i = blockIdx.x * blockDim.x + threadIdx.x;
    if (i >= total) return;
    int c = (int)((i / (unsigned)plane) % (unsigned)C);
    float v = __fsub_rn(x[i], g_mean[c]);
    v = __fdiv_rn(v, g_sdev[c]);
    v = __fmul_rn(v, __ldg(&g[c]));
    v = __fadd_rn(v, __ldg(&be[c]));
    if (relu) v = fmaxf(v, 0.f);
    x[i] = v;
}

// ------------------------------ Encoder convs (bit-exact chains) ------------

template<int CI>
__global__ void k_conv_k4s2_t(const float* __restrict__ in, const float* __restrict__ w,
                              const float* __restrict__ bias, float* __restrict__ out,
                              int CO, int HI, int WI) {
    int HO = HI >> 1, WO = WI >> 1;
    unsigned total = (unsigned)N_BATCH * CO * HO * WO;
    unsigned idx = blockIdx.x * blockDim.x + threadIdx.x;
    if (idx >= total) return;
    int ox = (int)(idx % (unsigned)WO);
    unsigned t = idx / (unsigned)WO;
    int oy = (int)(t % (unsigned)HO); t /= (unsigned)HO;
    int co = (int)(t % (unsigned)CO);
    int n  = (int)(t / (unsigned)CO);

    const float* ibase = in + ((long)n * CI) * HI * WI;
    const float* wbase = w + ((long)co * CI) * 16;
    long cs = (long)HI * WI;

    float acc0 = 0.f, acc1 = 0.f;
    bool interior = (oy >= 1) & (oy < HO - 1) & (ox >= 1) & (ox < WO - 1);
    if (interior) {
        const float* ip0 = ibase + (long)(oy * 2 - 1) * WI + (ox * 2 - 1);
#pragma unroll
        for (int ci = 0; ci < CI; ci++) {
            const float* ip = ip0 + ci * cs;
            const float* wp = wbase + ci * 16;
            float a = (ci & 1) ? acc1 : acc0;
#pragma unroll
            for (int kh = 0; kh < 4; kh++)
#pragma unroll
                for (int kw = 0; kw < 4; kw++)
                    a = fmaf(__ldg(&ip[kh * WI + kw]), __ldg(&wp[kh * 4 + kw]), a);
            if (ci & 1) acc1 = a; else acc0 = a;
        }
    } else {
#pragma unroll
        for (int ci = 0; ci < CI; ci++) {
            const float* ip = ibase + ci * cs;
            const float* wp = wbase + ci * 16;
            float a = (ci & 1) ? acc1 : acc0;
#pragma unroll
            for (int kh = 0; kh < 4; kh++) {
                int iy = oy * 2 + kh - 1;
                if ((unsigned)iy >= (unsigned)HI) continue;
#pragma unroll
                for (int kw = 0; kw < 4; kw++) {
                    int ix = ox * 2 + kw - 1;
                    if ((unsigned)ix >= (unsigned)WI) continue;
                    a = fmaf(__ldg(&ip[iy * WI + ix]), __ldg(&wp[kh * 4 + kw]), a);
                }
            }
            if (ci & 1) acc1 = a; else acc0 = a;
        }
    }
    out[idx] = __fadd_rn(__fadd_rn(acc0, acc1), __ldg(&bias[co]));
}

template<int CI>
__global__ void k_conv1x1_t(const float* __restrict__ in, const float* __restrict__ w,
                            const float* __restrict__ bias, float* __restrict__ out,
                            int CO, int plane) {
    unsigned total = (unsigned)N_BATCH * CO * plane;
    unsigned idx = blockIdx.x * blockDim.x + threadIdx.x;
    if (idx >= total) return;
    int p  = (int)(idx % (unsigned)plane);
    unsigned t = idx / (unsigned)plane;
    int co = (int)(t % (unsigned)CO);
    int n  = (int)(t / (unsigned)CO);
    const float* ip = in + ((long)n * CI) * plane + p;
    const float* wp = w + (long)co * CI;
    float acc0 = 0.f, acc1 = 0.f;
#pragma unroll
    for (int ci = 0; ci < CI; ci += 2) {
        acc0 = fmaf(__ldg(&ip[(long)ci * plane]),       __ldg(&wp[ci]),     acc0);
        acc1 = fmaf(__ldg(&ip[(long)(ci + 1) * plane]), __ldg(&wp[ci + 1]), acc1);
    }
    out[idx] = __fadd_rn(__fadd_rn(acc0, acc1), __ldg(&bias[co]));
}

// ------------------------------ Decoder tconv: multi-co quad ----------------
// Thread computes 2x2 outputs for COG consecutive co's; window loaded once.

template<int CI, int COG>
__global__ void k_tconv_multi(const float* __restrict__ in, const float* __restrict__ w,
                              const float* __restrict__ bias, float* __restrict__ out,
                              int CO, int HI, int WI) {
    int co0 = blockIdx.y * COG;
    int n   = blockIdx.z;
    __shared__ float ws[COG][CI * 16];
    for (int i = threadIdx.x; i < COG * CI * 16; i += blockDim.x) {
        int g = i / (CI * 16);
        int r = i - g * (CI * 16);
        int ci = r >> 4, tp = r & 15;
        ws[g][r] = w[((long)ci * CO + (co0 + g)) * 16 + tp];
    }
    __syncthreads();

    int q = blockIdx.x * blockDim.x + threadIdx.x;
    if (q >= HI * WI) return;
    int qx = q % WI, qy = q / WI;
    const float* ib = in + ((long)n * CI) * HI * WI;
    long cs = (long)HI * WI;

    float acc[COG][4];
#pragma unroll
    for (int g = 0; g < COG; g++)
#pragma unroll
        for (int s = 0; s < 4; s++) acc[g][s] = 0.f;

#pragma unroll 2
    for (int ci = 0; ci < CI; ci++) {
        const float* ip = ib + ci * cs;
        float a[3][3];
#pragma unroll
        for (int dy = 0; dy < 3; dy++) {
            int iy = qy + dy - 1;
#pragma unroll
            for (int dx = 0; dx < 3; dx++) {
                int ix = qx + dx - 1;
                a[dy][dx] = ((unsigned)iy < (unsigned)HI && (unsigned)ix < (unsigned)WI)
                          ? __ldg(&ip[iy * WI + ix]) : 0.f;
            }
        }
#pragma unroll
        for (int g = 0; g < COG; g++) {
            const float* wp = &ws[g][ci * 16];
#pragma unroll
            for (int sy = 0; sy < 2; sy++) {
                int khr = (sy + 1) & 1;
#pragma unroll
                for (int sx = 0; sx < 2; sx++) {
                    int kwr = (sx + 1) & 1;
#pragma unroll
                    for (int kh = khr; kh < 4; kh += 2) {
                        int dy = ((sy + 1 - kh) >> 1) + 1;
#pragma unroll
                        for (int kw = kwr; kw < 4; kw += 2) {
                            int dx = ((sx + 1 - kw) >> 1) + 1;
                            acc[g][sy * 2 + sx] = fmaf(a[dy][dx], wp[kh * 4 + kw],
                                                       acc[g][sy * 2 + sx]);
                        }
                    }
                }
            }
        }
    }
    int HO = HI << 1, WO = WI << 1;
#pragma unroll
    for (int g = 0; g < COG; g++) {
        float b = __ldg(&bias[co0 + g]);
        long obase = ((long)(n * CO + co0 + g)) * HO * WO;
#pragma unroll
        for (int sy = 0; sy < 2; sy++)
#pragma unroll
            for (int sx = 0; sx < 2; sx++)
                out[obase + (long)(2 * qy + sy) * WO + (2 * qx + sx)] =
                    acc[g][sy * 2 + sx] + b;
    }
}

// ------------------------------ VQ (bit-exact) ------------------------------

__global__ void k_emb_norms(const float* __restrict__ emb) {
    int k = blockIdx.x * blockDim.x + threadIdx.x;
    if (k >= 512) return;
    const float* e = emb + k * 32;
    float s = 0.f;
#pragma unroll
    for (int c = 0; c < 32; c++)
        s = __fadd_rn(s, __fmul_rn(e[c], e[c]));
    g_e2[k] = s;
}

__global__ void k_vq(const float* __restrict__ ze, const float* __restrict__ emb) {
    int pos = blockIdx.x * blockDim.x + threadIdx.x;
    if (pos >= 32768) return;
    int p = pos & 1023;
    int n = pos >> 10;
    float z[32];
#pragma unroll
    for (int c = 0; c < 32; c++)
        z[c] = ze[(((long)(n * 32 + c)) << 10) + p];

    float t = 0.f;
#pragma unroll
    for (int c = 0; c < 32; c++)
        t = __fadd_rn(t, __fmul_rn(z[c], z[c]));

    float best = 3.402823e38f;
    int bi = 0;
    for (int k = 0; k < 512; k++) {
        const float* e = emb + k * 32;
        float u = 0.f;
#pragma unroll
        for (int c = 0; c < 32; c++)
            u = fmaf(z[c], __ldg(&e[c]), u);
        float r = __fsub_rn(t, __fmul_rn(2.0f, u));
        float d = __fadd_rn(r, __ldg(&g_e2[k]));
        if (d < best) { best = d; bi = k; }
    }
    g_lat[pos] = bi;
    const float* e = emb + bi * 32;
#pragma unroll
    for (int c = 0; c < 32; c++)
        g_zq[(((long)(n * 32 + c)) << 10) + p] = __ldg(&e[c]);
}

// ------------------------------ Output packing -----------------------------

__global__ void k_write_outputs(float* __restrict__ out) {
    const long ZE = 1048576, ZQ = 1048576, LAT = 32768;
    const long OFF = 62914560;
    long i = (long)blockIdx.x * blockDim.x + threadIdx.x;
    if (i < ZE) {
        out[OFF + i] = g_ze[i];
    } else if (i < ZE + ZQ) {
        long j = i - ZE;
        out[OFF + ZE + j] = g_zq[j];
    } else if (i < ZE + ZQ + LAT) {
        long j = i - ZE - ZQ;
        out[OFF + ZE + ZQ + j] = (float)g_lat[j];
    }
}

// ------------------------------ Host orchestration -------------------------

static inline int nblk(long total, int bs) { return (int)((total + bs - 1) / bs); }

// encoder BN: bit-exact two-pass
static void run_bn(float* buf, const float* g, const float* be, int C, int plane, int relu) {
    long count = (long)N_BATCH * plane;
    float inv_n = 1.0f / (float)count;
    unsigned total = (unsigned)((long)C * count);
    k_bn_partial<<<C * SL, 256>>>(buf, C, plane, 0);
    k_bn_combine<<<1, 64>>>(C, inv_n, 0);
    k_bn_partial<<<C * SL, 256>>>(buf, C, plane, 1);
    k_bn_combine<<<1, 64>>>(C, inv_n, 1);
    k_bn_apply<<<nblk(total, 256), 256>>>(buf, g, be, C, plane, total, relu);
}

// decoder BN: fused single-pass (1e-3 tolerance)
static void run_bn_dec(float* buf, const float* g, const float* be, int C, int plane, int relu) {
    long count = (long)N_BATCH * plane;
    float inv_n = 1.0f / (float)count;
    unsigned total = (unsigned)((long)C * count);
    k_bn_partial2<<<C * SL, 256>>>(buf, C, plane);
    k_bn_combine2<<<1, 64>>>(C, inv_n);
    k_bn_apply<<<nblk(total, 256), 256>>>(buf, g, be, C, plane, total, relu);
}

extern "C" void kernel_launch(void* const* d_in, const int* in_sizes, int n_in,
                              void* d_out, int out_size) {
    const float* x   = (const float*)d_in[0];
    const float* w1  = (const float*)d_in[1];
    const float* b1  = (const float*)d_in[2];
    const float* g1  = (const float*)d_in[3];
    const float* be1 = (const float*)d_in[4];
    const float* w2  = (const float*)d_in[5];
    const float* b2  = (const float*)d_in[6];
    const float* g2  = (const float*)d_in[7];
    const float* be2 = (const float*)d_in[8];
    const float* w3  = (const float*)d_in[9];
    const float* b3  = (const float*)d_in[10];
    const float* g3  = (const float*)d_in[11];
    const float* be3 = (const float*)d_in[12];
    const float* w4  = (const float*)d_in[13];
    const float* b4  = (const float*)d_in[14];
    const float* g4  = (const float*)d_in[15];
    const float* be4 = (const float*)d_in[16];
    const float* emb = (const float*)d_in[17];
    const float* dw1 = (const float*)d_in[18];
    const float* db1 = (const float*)d_in[19];
    const float* dg1 = (const float*)d_in[20];
    const float* dbe1= (const float*)d_in[21];
    const float* tw1 = (const float*)d_in[22];
    const float* tb1 = (const float*)d_in[23];
    const float* tg1 = (const float*)d_in[24];
    const float* tbe1= (const float*)d_in[25];
    const float* tw2 = (const float*)d_in[26];
    const float* tb2 = (const float*)d_in[27];
    const float* tg2 = (const float*)d_in[28];
    const float* tbe2= (const float*)d_in[29];
    const float* tw3 = (const float*)d_in[30];
    const float* tb3 = (const float*)d_in[31];

    float* out = (float*)d_out;

    float *h1, *h2, *h3, *ze, *zq, *d1, *t1, *t2;
    cudaGetSymbolAddress((void**)&h1, g_h1);
    cudaGetSymbolAddress((void**)&h2, g_h2);
    cudaGetSymbolAddress((void**)&h3, g_h3);
    cudaGetSymbolAddress((void**)&ze, g_ze);
    cudaGetSymbolAddress((void**)&zq, g_zq);
    cudaGetSymbolAddress((void**)&d1, g_d1);
    cudaGetSymbolAddress((void**)&t1, g_t1);
    cudaGetSymbolAddress((void**)&t2, g_t2);

    // ---- Encoder (bit-exact) ----
    k_conv_k4s2_t<1><<<nblk(8388608, 256), 256>>>(x, w1, b1, h1, 16, 256, 256);
    run_bn(h1, g1, be1, 16, 128 * 128, 1);

    k_conv_k4s2_t<16><<<nblk(4194304, 256), 256>>>(h1, w2, b2, h2, 32, 128, 128);
    run_bn(h2, g2, be2, 32, 64 * 64, 1);

    k_conv_k4s2_t<32><<<nblk(2097152, 256), 256>>>(h2, w3, b3, h3, 64, 64, 64);
    run_bn(h3, g3, be3, 64, 32 * 32, 1);

    k_conv1x1_t<64><<<nblk(1048576, 256), 256>>>(h3, w4, b4, ze, 32, 1024);
    run_bn(ze, g4, be4, 32, 32 * 32, 0);

    // ---- VQ (bit-exact) ----
    k_emb_norms<<<2, 256>>>(emb);
    k_vq<<<nblk(32768, 256), 256>>>(ze, emb);

    // ---- Decoder (1e-3 tolerance) ----
    k_conv1x1_t<32><<<nblk(2097152, 256), 256>>>(zq, dw1, db1, d1, 64, 1024);
    run_bn_dec(d1, dg1, dbe1, 64, 32 * 32, 1);

    {   // tconv1: 64->32, 32x32 -> 64x64  (COG=4, 8 groups)
        dim3 gr(nblk(32 * 32, 256), 8, N_BATCH);
        k_tconv_multi<64, 4><<<gr, 256>>>(d1, tw1, tb1, t1, 32, 32, 32);
    }
    run_bn_dec(t1, tg1, tbe1, 32, 64 * 64, 1);

    {   // tconv2: 32->16, 64x64 -> 128x128  (COG=4, 4 groups)
        dim3 gr(nblk(64 * 64, 256), 4, N_BATCH);
        k_tconv_multi<32, 4><<<gr, 256>>>(t1, tw2, tb2, t2, 16, 64, 64);
    }
    run_bn_dec(t2, tg2, tbe2, 16, 128 * 128, 1);

    {   // tconv3: 16->30, 128x128 -> 256x256  (COG=6, 5 groups)
        dim3 gr(nblk(128 * 128, 256), 5, N_BATCH);
        k_tconv_multi<16, 6><<<gr, 256>>>(t2, tw3, tb3, out, 30, 128, 128);
    }

    // ---- Pack auxiliary outputs ----
    if ((long)out_size >= 65044480L) {
        k_write_outputs<<<nblk(2129920, 256), 256>>>(out);
    }
}

// round 17
// speedup vs baseline: 1.3180x; 1.3180x over previous
#include <cuda_runtime.h>
#include <cuda_bf16.h>
#include <math.h>

// ---------------------------------------------------------------------------
// VQ-VAE forward. Encoder path (convs, BN two-pass, VQ distance chain) is
// bit-load-bearing: byte-identical value sequences to the R14/R15 passing
// config. Decoder (1e-3): quad tconv with COG=2, fused single-pass BN.
// VQ: 8 lanes per position, 64 codes each, width-8 shuffle-min with explicit
// lower-index tie-break == sequential first-index argmin (bit-identical).
// ---------------------------------------------------------------------------

#define N_BATCH 32
#define SL 32

__device__ float g_h1[8388608];
__device__ float g_h2[4194304];
__device__ float g_h3[2097152];
__device__ float g_ze[1048576];
__device__ float g_zq[1048576];
__device__ int   g_lat[32768];
__device__ float g_d1[2097152];
__device__ float g_t1[4194304];
__device__ float g_t2[8388608];

__device__ float g_part[64 * SL];
__device__ float g_part2[64 * SL];
__device__ float g_mean[64];
__device__ float g_sdev[64];
__device__ float g_e2[512];

// ------------------------------ BatchNorm (encoder: bit-exact two-pass) -----

__global__ void k_bn_partial(const float* __restrict__ x, int C, int plane, int pass) {
    int c = blockIdx.x / SL;
    int s = blockIdx.x % SL;
    unsigned per = (unsigned)N_BATCH * (unsigned)plane;
    float m = (pass == 1) ? g_mean[c] : 0.f;
    float acc = 0.f;
    unsigned step = (unsigned)SL * blockDim.x;
    for (unsigned i = (unsigned)s * blockDim.x + threadIdx.x; i < per; i += step) {
        unsigned n = i / (unsigned)plane;
        unsigned p = i - n * (unsigned)plane;
        float v = x[((unsigned)(n * C + c)) * (unsigned)plane + p];
        if (pass == 1) { float d = __fsub_rn(v, m); acc = __fadd_rn(acc, __fmul_rn(d, d)); }
        else           { acc = __fadd_rn(acc, v); }
    }
    __shared__ float ss[256];
    ss[threadIdx.x] = acc;
    __syncthreads();
    for (int st = 128; st > 0; st >>= 1) {
        if (threadIdx.x < st) ss[threadIdx.x] = __fadd_rn(ss[threadIdx.x], ss[threadIdx.x + st]);
        __syncthreads();
    }
    if (threadIdx.x == 0) g_part[c * SL + s] = ss[0];
}

__global__ void k_bn_combine(int C, float inv_n, int pass) {
    int c = threadIdx.x;
    if (c >= C) return;
    float s = 0.f;
#pragma unroll 1
    for (int i = 0; i < SL; i++) s = __fadd_rn(s, g_part[c * SL + i]);
    float v = __fmul_rn(s, inv_n);
    if (pass == 0) g_mean[c] = v;
    else           g_sdev[c] = __fsqrt_rn(__fadd_rn(v, 1e-5f));
}

// ------------------------------ BatchNorm (decoder: fused single-pass) ------

__global__ void k_bn_partial2(const float* __restrict__ x, int C, int plane) {
    int c = blockIdx.x / SL;
    int s = blockIdx.x % SL;
    unsigned per = (unsigned)N_BATCH * (unsigned)plane;
    float acc = 0.f, acc2 = 0.f;
    unsigned step = (unsigned)SL * blockDim.x;
    for (unsigned i = (unsigned)s * blockDim.x + threadIdx.x; i < per; i += step) {
        unsigned n = i / (unsigned)plane;
        unsigned p = i - n * (unsigned)plane;
        float v = x[((unsigned)(n * C + c)) * (unsigned)plane + p];
        acc  += v;
        acc2 = fmaf(v, v, acc2);
    }
    __shared__ float ss[256], s2[256];
    ss[threadIdx.x] = acc; s2[threadIdx.x] = acc2;
    __syncthreads();
    for (int st = 128; st > 0; st >>= 1) {
        if (threadIdx.x < st) {
            ss[threadIdx.x] += ss[threadIdx.x + st];
            s2[threadIdx.x] += s2[threadIdx.x + st];
        }
        __syncthreads();
    }
    if (threadIdx.x == 0) {
        g_part[c * SL + s]  = ss[0];
        g_part2[c * SL + s] = s2[0];
    }
}

__global__ void k_bn_combine2(int C, float inv_n) {
    int c = threadIdx.x;
    if (c >= C) return;
    float s = 0.f, q = 0.f;
#pragma unroll 1
    for (int i = 0; i < SL; i++) { s += g_part[c * SL + i]; q += g_part2[c * SL + i]; }
    float m = s * inv_n;
    float var = fmaf(-m, m, q * inv_n);
    g_mean[c] = m;
    g_sdev[c] = __fsqrt_rn(var + 1e-5f);
}

// Vectorized apply: elementwise map, per-element ops identical -> bit-safe.
__global__ void k_bn_apply4(float4* __restrict__ x, const float* __restrict__ g,
                            const float* __restrict__ be,
                            int C, int plane4, unsigned total4, int relu) {
    unsigned i = blockIdx.x * blockDim.x + threadIdx.x;
    if (i >= total4) return;
    int c = (int)((i / (unsigned)plane4) % (unsigned)C);
    float m = g_mean[c], sd = g_sdev[c];
    float gg = __ldg(&g[c]), bb = __ldg(&be[c]);
    float4 v = x[i];
    float* f = (float*)&v;
#pragma unroll
    for (int j = 0; j < 4; j++) {
        float t = __fsub_rn(f[j], m);
        t = __fdiv_rn(t, sd);
        t = __fmul_rn(t, gg);
        t = __fadd_rn(t, bb);
        if (relu) t = fmaxf(t, 0.f);
        f[j] = t;
    }
    x[i] = v;
}

// ------------------------------ Encoder convs (bit-exact chains) ------------

template<int CI>
__global__ void k_conv_k4s2_t(const float* __restrict__ in, const float* __restrict__ w,
                              const float* __restrict__ bias, float* __restrict__ out,
                              int CO, int HI, int WI) {
    int HO = HI >> 1, WO = WI >> 1;
    unsigned total = (unsigned)N_BATCH * CO * HO * WO;
    unsigned idx = blockIdx.x * blockDim.x + threadIdx.x;
    if (idx >= total) return;
    int ox = (int)(idx % (unsigned)WO);
    unsigned t = idx / (unsigned)WO;
    int oy = (int)(t % (unsigned)HO); t /= (unsigned)HO;
    int co = (int)(t % (unsigned)CO);
    int n  = (int)(t / (unsigned)CO);

    const float* ibase = in + ((long)n * CI) * HI * WI;
    const float* wbase = w + ((long)co * CI) * 16;
    long cs = (long)HI * WI;

    float acc0 = 0.f, acc1 = 0.f;
    bool interior = (oy >= 1) & (oy < HO - 1) & (ox >= 1) & (ox < WO - 1);
    if (interior) {
        const float* ip0 = ibase + (long)(oy * 2 - 1) * WI + (ox * 2 - 1);
#pragma unroll
        for (int ci = 0; ci < CI; ci++) {
            const float* ip = ip0 + ci * cs;
            const float* wp = wbase + ci * 16;
            float a = (ci & 1) ? acc1 : acc0;
#pragma unroll
            for (int kh = 0; kh < 4; kh++)
#pragma unroll
                for (int kw = 0; kw < 4; kw++)
                    a = fmaf(__ldg(&ip[kh * WI + kw]), __ldg(&wp[kh * 4 + kw]), a);
            if (ci & 1) acc1 = a; else acc0 = a;
        }
    } else {
#pragma unroll
        for (int ci = 0; ci < CI; ci++) {
            const float* ip = ibase + ci * cs;
            const float* wp = wbase + ci * 16;
            float a = (ci & 1) ? acc1 : acc0;
#pragma unroll
            for (int kh = 0; kh < 4; kh++) {
                int iy = oy * 2 + kh - 1;
                if ((unsigned)iy >= (unsigned)HI) continue;
#pragma unroll
                for (int kw = 0; kw < 4; kw++) {
                    int ix = ox * 2 + kw - 1;
                    if ((unsigned)ix >= (unsigned)WI) continue;
                    a = fmaf(__ldg(&ip[iy * WI + ix]), __ldg(&wp[kh * 4 + kw]), a);
                }
            }
            if (ci & 1) acc1 = a; else acc0 = a;
        }
    }
    out[idx] = __fadd_rn(__fadd_rn(acc0, acc1), __ldg(&bias[co]));
}

template<int CI>
__global__ void k_conv1x1_t(const float* __restrict__ in, const float* __restrict__ w,
                            const float* __restrict__ bias, float* __restrict__ out,
                            int CO, int plane) {
    unsigned total = (unsigned)N_BATCH * CO * plane;
    unsigned idx = blockIdx.x * blockDim.x + threadIdx.x;
    if (idx >= total) return;
    int p  = (int)(idx % (unsigned)plane);
    unsigned t = idx / (unsigned)plane;
    int co = (int)(t % (unsigned)CO);
    int n  = (int)(t / (unsigned)CO);
    const float* ip = in + ((long)n * CI) * plane + p;
    const float* wp = w + (long)co * CI;
    float acc0 = 0.f, acc1 = 0.f;
#pragma unroll
    for (int ci = 0; ci < CI; ci += 2) {
        acc0 = fmaf(__ldg(&ip[(long)ci * plane]),       __ldg(&wp[ci]),     acc0);
        acc1 = fmaf(__ldg(&ip[(long)(ci + 1) * plane]), __ldg(&wp[ci + 1]), acc1);
    }
    out[idx] = __fadd_rn(__fadd_rn(acc0, acc1), __ldg(&bias[co]));
}

// ------------------------------ Decoder tconv: quad, COG=2 ------------------

template<int CI>
__global__ void k_tconv_quad2(const float* __restrict__ in, const float* __restrict__ w,
                              const float* __restrict__ bias, float* __restrict__ out,
                              int CO, int HI, int WI) {
    int co0 = blockIdx.y * 2;
    int n   = blockIdx.z;
    __shared__ float ws[2][CI * 16];
    for (int i = threadIdx.x; i < 2 * CI * 16; i += blockDim.x) {
        int g = i / (CI * 16);
        int r = i - g * (CI * 16);
        ws[g][r] = w[((long)(r >> 4) * CO + (co0 + g)) * 16 + (r & 15)];
    }
    __syncthreads();

    int q = blockIdx.x * blockDim.x + threadIdx.x;
    if (q >= HI * WI) return;
    int qx = q % WI, qy = q / WI;
    const float* ib = in + ((long)n * CI) * HI * WI;
    long cs = (long)HI * WI;

    float acc[2][4] = {{0.f,0.f,0.f,0.f},{0.f,0.f,0.f,0.f}};
#pragma unroll 4
    for (int ci = 0; ci < CI; ci++) {
        const float* ip = ib + ci * cs;
        float a[3][3];
#pragma unroll
        for (int dy = 0; dy < 3; dy++) {
            int iy = qy + dy - 1;
#pragma unroll
            for (int dx = 0; dx < 3; dx++) {
                int ix = qx + dx - 1;
                a[dy][dx] = ((unsigned)iy < (unsigned)HI && (unsigned)ix < (unsigned)WI)
                          ? __ldg(&ip[iy * WI + ix]) : 0.f;
            }
        }
#pragma unroll
        for (int g = 0; g < 2; g++) {
            const float* wp = &ws[g][ci * 16];
#pragma unroll
            for (int sy = 0; sy < 2; sy++) {
                int khr = (sy + 1) & 1;
#pragma unroll
                for (int sx = 0; sx < 2; sx++) {
                    int kwr = (sx + 1) & 1;
#pragma unroll
                    for (int kh = khr; kh < 4; kh += 2) {
                        int dy = ((sy + 1 - kh) >> 1) + 1;
#pragma unroll
                        for (int kw = kwr; kw < 4; kw += 2) {
                            int dx = ((sx + 1 - kw) >> 1) + 1;
                            acc[g][sy * 2 + sx] = fmaf(a[dy][dx], wp[kh * 4 + kw],
                                                       acc[g][sy * 2 + sx]);
                        }
                    }
                }
            }
        }
    }
    int HO = HI << 1, WO = WI << 1;
#pragma unroll
    for (int g = 0; g < 2; g++) {
        float b = __ldg(&bias[co0 + g]);
        long obase = ((long)(n * CO + co0 + g)) * HO * WO;
#pragma unroll
        for (int sy = 0; sy < 2; sy++)
#pragma unroll
            for (int sx = 0; sx < 2; sx++)
                out[obase + (long)(2 * qy + sy) * WO + (2 * qx + sx)] =
                    acc[g][sy * 2 + sx] + b;
    }
}

// ------------------------------ VQ (bit-exact, 8-way split-k) ---------------

__global__ void k_emb_norms(const float* __restrict__ emb) {
    int k = blockIdx.x * blockDim.x + threadIdx.x;
    if (k >= 512) return;
    const float* e = emb + k * 32;
    float s = 0.f;
#pragma unroll
    for (int c = 0; c < 32; c++)
        s = __fadd_rn(s, __fmul_rn(e[c], e[c]));
    g_e2[k] = s;
}

// 8 lanes per position; lane l scans k in [64l, 64l+64) with the exact
// sequential chain; width-8 shuffle-min with lower-index preference on ties
// == global first-index argmin over bitwise-identical d's.
__global__ void k_vq8(const float* __restrict__ ze, const float* __restrict__ emb) {
    unsigned tid = blockIdx.x * blockDim.x + threadIdx.x;
    unsigned pos = tid >> 3;
    int l8 = (int)(tid & 7u);
    if (pos >= 32768u) return;
    int p = (int)(pos & 1023u);
    int n = (int)(pos >> 10);

    float z[32];
#pragma unroll
    for (int c = 0; c < 32; c++)
        z[c] = ze[(((long)(n * 32 + c)) << 10) + p];

    float t = 0.f;
#pragma unroll
    for (int c = 0; c < 32; c++)
        t = __fadd_rn(t, __fmul_rn(z[c], z[c]));

    float best = 3.402823e38f;
    int bi = 0x7fffffff;
    int k0 = l8 * 64;
    for (int k = k0; k < k0 + 64; k++) {
        const float* e = emb + k * 32;
        float u = 0.f;
#pragma unroll
        for (int c = 0; c < 32; c++)
            u = fmaf(z[c], __ldg(&e[c]), u);
        float r = __fsub_rn(t, __fmul_rn(2.0f, u));
        float d = __fadd_rn(r, __ldg(&g_e2[k]));
        if (d < best) { best = d; bi = k; }
    }
#pragma unroll
    for (int off = 4; off >= 1; off >>= 1) {
        float ob = __shfl_down_sync(0xffffffffu, best, off, 8);
        int  obi = __shfl_down_sync(0xffffffffu, bi,   off, 8);
        if (ob < best || (ob == best && obi < bi)) { best = ob; bi = obi; }
    }
    bi = __shfl_sync(0xffffffffu, bi, 0, 8);   // broadcast winner to all 8 lanes

    if (l8 == 0) g_lat[pos] = bi;
    const float* e = emb + bi * 32;
#pragma unroll
    for (int j = 0; j < 4; j++) {
        int c = l8 * 4 + j;
        g_zq[(((long)(n * 32 + c)) << 10) + p] = __ldg(&e[c]);
    }
}

// ------------------------------ Output packing (vectorized) -----------------

__global__ void k_write_outputs4(float4* __restrict__ out) {
    const unsigned ZE4 = 262144, ZQ4 = 262144, LAT4 = 8192;
    const unsigned OFF4 = 15728640;
    unsigned i = blockIdx.x * blockDim.x + threadIdx.x;
    if (i < ZE4) {
        out[OFF4 + i] = ((const float4*)g_ze)[i];
    } else if (i < ZE4 + ZQ4) {
        unsigned j = i - ZE4;
        out[OFF4 + ZE4 + j] = ((const float4*)g_zq)[j];
    } else if (i < ZE4 + ZQ4 + LAT4) {
        unsigned j = i - ZE4 - ZQ4;
        const int* lp = &g_lat[j * 4];
        float4 v = make_float4((float)lp[0], (float)lp[1], (float)lp[2], (float)lp[3]);
        out[OFF4 + ZE4 + ZQ4 + j] = v;
    }
}

// ------------------------------ Host orchestration -------------------------

static inline int nblk(long total, int bs) { return (int)((total + bs - 1) / bs); }

static void run_bn(float* buf, const float* g, const float* be, int C, int plane, int relu) {
    long count = (long)N_BATCH * plane;
    float inv_n = 1.0f / (float)count;
    unsigned total4 = (unsigned)((long)C * count / 4);
    k_bn_partial<<<C * SL, 256>>>(buf, C, plane, 0);
    k_bn_combine<<<1, 64>>>(C, inv_n, 0);
    k_bn_partial<<<C * SL, 256>>>(buf, C, plane, 1);
    k_bn_combine<<<1, 64>>>(C, inv_n, 1);
    k_bn_apply4<<<nblk(total4, 256), 256>>>((float4*)buf, g, be, C, plane / 4, total4, relu);
}

static void run_bn_dec(float* buf, const float* g, const float* be, int C, int plane, int relu) {
    long count = (long)N_BATCH * plane;
    float inv_n = 1.0f / (float)count;
    unsigned total4 = (unsigned)((long)C * count / 4);
    k_bn_partial2<<<C * SL, 256>>>(buf, C, plane);
    k_bn_combine2<<<1, 64>>>(C, inv_n);
    k_bn_apply4<<<nblk(total4, 256), 256>>>((float4*)buf, g, be, C, plane / 4, total4, relu);
}

extern "C" void kernel_launch(void* const* d_in, const int* in_sizes, int n_in,
                              void* d_out, int out_size) {
    const float* x   = (const float*)d_in[0];
    const float* w1  = (const float*)d_in[1];
    const float* b1  = (const float*)d_in[2];
    const float* g1  = (const float*)d_in[3];
    const float* be1 = (const float*)d_in[4];
    const float* w2  = (const float*)d_in[5];
    const float* b2  = (const float*)d_in[6];
    const float* g2  = (const float*)d_in[7];
    const float* be2 = (const float*)d_in[8];
    const float* w3  = (const float*)d_in[9];
    const float* b3  = (const float*)d_in[10];
    const float* g3  = (const float*)d_in[11];
    const float* be3 = (const float*)d_in[12];
    const float* w4  = (const float*)d_in[13];
    const float* b4  = (const float*)d_in[14];
    const float* g4  = (const float*)d_in[15];
    const float* be4 = (const float*)d_in[16];
    const float* emb = (const float*)d_in[17];
    const float* dw1 = (const float*)d_in[18];
    const float* db1 = (const float*)d_in[19];
    const float* dg1 = (const float*)d_in[20];
    const float* dbe1= (const float*)d_in[21];
    const float* tw1 = (const float*)d_in[22];
    const float* tb1 = (const float*)d_in[23];
    const float* tg1 = (const float*)d_in[24];
    const float* tbe1= (const float*)d_in[25];
    const float* tw2 = (const float*)d_in[26];
    const float* tb2 = (const float*)d_in[27];
    const float* tg2 = (const float*)d_in[28];
    const float* tbe2= (const float*)d_in[29];
    const float* tw3 = (const float*)d_in[30];
    const float* tb3 = (const float*)d_in[31];

    float* out = (float*)d_out;

    float *h1, *h2, *h3, *ze, *zq, *d1, *t1, *t2;
    cudaGetSymbolAddress((void**)&h1, g_h1);
    cudaGetSymbolAddress((void**)&h2, g_h2);
    cudaGetSymbolAddress((void**)&h3, g_h3);
    cudaGetSymbolAddress((void**)&ze, g_ze);
    cudaGetSymbolAddress((void**)&zq, g_zq);
    cudaGetSymbolAddress((void**)&d1, g_d1);
    cudaGetSymbolAddress((void**)&t1, g_t1);
    cudaGetSymbolAddress((void**)&t2, g_t2);

    // ---- Encoder (bit-exact) ----
    k_conv_k4s2_t<1><<<nblk(8388608, 256), 256>>>(x, w1, b1, h1, 16, 256, 256);
    run_bn(h1, g1, be1, 16, 128 * 128, 1);

    k_conv_k4s2_t<16><<<nblk(4194304, 256), 256>>>(h1, w2, b2, h2, 32, 128, 128);
    run_bn(h2, g2, be2, 32, 64 * 64, 1);

    k_conv_k4s2_t<32><<<nblk(2097152, 256), 256>>>(h2, w3, b3, h3, 64, 64, 64);
    run_bn(h3, g3, be3, 64, 32 * 32, 1);

    k_conv1x1_t<64><<<nblk(1048576, 256), 256>>>(h3, w4, b4, ze, 32, 1024);
    run_bn(ze, g4, be4, 32, 32 * 32, 0);

    // ---- VQ (bit-exact, 8-way) ----
    k_emb_norms<<<2, 256>>>(emb);
    k_vq8<<<nblk(32768 * 8, 256), 256>>>(ze, emb);

    // ---- Decoder (1e-3 tolerance) ----
    k_conv1x1_t<32><<<nblk(2097152, 256), 256>>>(zq, dw1, db1, d1, 64, 1024);
    run_bn_dec(d1, dg1, dbe1, 64, 32 * 32, 1);

    {   // tconv1: 64->32, 32x32 -> 64x64  (COG=2 -> 16 groups)
        dim3 gr(nblk(32 * 32, 256), 16, N_BATCH);
        k_tconv_quad2<64><<<gr, 256>>>(d1, tw1, tb1, t1, 32, 32, 32);
    }
    run_bn_dec(t1, tg1, tbe1, 32, 64 * 64, 1);

    {   // tconv2: 32->16, 64x64 -> 128x128  (COG=2 -> 8 groups)
        dim3 gr(nblk(64 * 64, 256), 8, N_BATCH);
        k_tconv_quad2<32><<<gr, 256>>>(t1, tw2, tb2, t2, 16, 64, 64);
    }
    run_bn_dec(t2, tg2, tbe2, 16, 128 * 128, 1);

    {   // tconv3: 16->30, 128x128 -> 256x256  (COG=2 -> 15 groups)
        dim3 gr(nblk(128 * 128, 256), 15, N_BATCH);
        k_tconv_quad2<16><<<gr, 256>>>(t2, tw3, tb3, out, 30, 128, 128);
    }

    // ---- Pack auxiliary outputs ----
    if ((long)out_size >= 65044480L) {
        k_write_outputs4<<<nblk(532480, 256), 256>>>((float4*)out);
    }
}